// round 7
// baseline (speedup 1.0000x reference)
#include <cuda_runtime.h>
#include <cuda_bf16.h>
#include <mma.h>
#include <cstdint>

using namespace nvcuda;

#define Bd   2
#define Cc   128
#define Hd   64
#define Wd   512
#define HW   (Hd*Wd)          // 32768
#define NPIX (Bd*HW)          // 65536
#define EPS  1e-5f

#define LDW   136             // bf16 leading dim in smem (272B rows, 16B-aligned)
#define LDSTG 132             // f32 stage leading dim

// ---------------- device scratch (allocation-free) ----------------
__device__ __align__(16) float         g_Y[Cc * NPIX];   // [o][gp]
__device__ __align__(16) __nv_bfloat16 g_Whi[Cc * Cc];   // [o][c] fw*scale_f, bf16 hi
__device__ __align__(16) __nv_bfloat16 g_Wlo[Cc * Cc];   // [o][c] residual lo
__device__ float  g_hf[Cc];
__device__ float4 g_pw4[Cc];                             // {pw*sp (x3), hp}
__device__ float4 g_ew4[Cc];                             // {ew*se (x3), 0}
__device__ float  g_she[3];

// ---------------------------------------------------------------- prep
__global__ void prep_kernel(const float* __restrict__ fw,
                            const float* __restrict__ fg, const float* __restrict__ fb,
                            const float* __restrict__ fm, const float* __restrict__ fv,
                            const float* __restrict__ pw,
                            const float* __restrict__ pg, const float* __restrict__ pb,
                            const float* __restrict__ pm, const float* __restrict__ pv,
                            const float* __restrict__ ew,
                            const float* __restrict__ eg, const float* __restrict__ eb,
                            const float* __restrict__ em, const float* __restrict__ ev) {
    const int tid = threadIdx.x;
    if (blockIdx.x < 64) {
        int i = (blockIdx.x << 8) + tid;      // 0..16383
        int o = i >> 7;
        float sf = fg[o] * rsqrtf(fv[o] + EPS);
        float w = fw[i] * sf;
        __nv_bfloat16 hi = __float2bfloat16(w);
        __nv_bfloat16 lo = __float2bfloat16(w - __bfloat162float(hi));
        g_Whi[i] = hi;
        g_Wlo[i] = lo;
    } else if (tid < Cc) {
        int o = tid;
        float sf = fg[o] * rsqrtf(fv[o] + EPS);
        g_hf[o] = fb[o] - fm[o] * sf;
        float sp = pg[o] * rsqrtf(pv[o] + EPS);
        float hp = pb[o] - pm[o] * sp;
        g_pw4[o] = make_float4(pw[3*o]*sp, pw[3*o+1]*sp, pw[3*o+2]*sp, hp);
        float se0 = eg[0] * rsqrtf(ev[0] + EPS);
        float se1 = eg[1] * rsqrtf(ev[1] + EPS);
        float se2 = eg[2] * rsqrtf(ev[2] + EPS);
        g_ew4[o] = make_float4(ew[o]*se0, ew[Cc+o]*se1, ew[2*Cc+o]*se2, 0.f);
        if (o < 3) {
            float se = eg[o] * rsqrtf(ev[o] + EPS);
            g_she[o] = eb[o] - em[o] * se;
        }
    }
}

// ---------------------------------------------------------------- pass1 (wmma / HMMA)
// D[128 out][128 px] = (Whi+Wlo) x (Fhi+Flo)^T, 3-term bf16 split, f32 accum.
// smem: Whi | Wlo | Fhi | Flo, each [128][LDW] bf16. Stage (f32 [128][LDSTG]) reuses.
#define SEG_BYTES (128 * LDW * 2)           // 34816
#define SM_TOT    (4 * SEG_BYTES)           // 139264

__global__ void __launch_bounds__(256, 1)
pass1_wmma(const float* __restrict__ feat) {
    extern __shared__ __align__(16) char sm[];
    __nv_bfloat16* Whi = (__nv_bfloat16*)(sm);
    __nv_bfloat16* Wlo = (__nv_bfloat16*)(sm + SEG_BYTES);
    __nv_bfloat16* Fhi = (__nv_bfloat16*)(sm + 2 * SEG_BYTES);
    __nv_bfloat16* Flo = (__nv_bfloat16*)(sm + 3 * SEG_BYTES);

    const int tid = threadIdx.x;
    const int gp0 = blockIdx.x << 7;
    const int b   = gp0 >> 15;
    const int p0  = gp0 & (HW - 1);

    // ---- copy W hi/lo into padded smem (row r: 16 float4) ----
    {
        const float4* shi = (const float4*)g_Whi;
        const float4* slo = (const float4*)g_Wlo;
        #pragma unroll
        for (int it = 0; it < 8; it++) {
            int idx = tid + (it << 8);           // 0..2047
            int r = idx >> 4, s = idx & 15;
            ((float4*)((char*)Whi + r * (LDW * 2)))[s] = shi[r * 16 + s];
            ((float4*)((char*)Wlo + r * (LDW * 2)))[s] = slo[r * 16 + s];
        }
    }

    // ---- convert F tile fp32 -> bf16 hi/lo into [px][k] padded smem ----
    {
        const float* fbase = feat + b * Cc * HW + p0;
        const int px = tid & 127;
        const int kg = tid >> 7;                 // 0/1 (k half)
        char* fhiRow = (char*)Fhi + px * (LDW * 2);
        char* floRow = (char*)Flo + px * (LDW * 2);
        #pragma unroll 8
        for (int j = 0; j < 32; j++) {
            int k = kg * 64 + 2 * j;
            float f0 = __ldg(fbase + k * HW + px);
            float f1 = __ldg(fbase + (k + 1) * HW + px);
            __nv_bfloat16 h0 = __float2bfloat16(f0);
            __nv_bfloat16 h1 = __float2bfloat16(f1);
            __nv_bfloat16 l0 = __float2bfloat16(f0 - __bfloat162float(h0));
            __nv_bfloat16 l1 = __float2bfloat16(f1 - __bfloat162float(h1));
            uint32_t vh = (uint32_t)__bfloat16_as_ushort(h0) | ((uint32_t)__bfloat16_as_ushort(h1) << 16);
            uint32_t vl = (uint32_t)__bfloat16_as_ushort(l0) | ((uint32_t)__bfloat16_as_ushort(l1) << 16);
            *(uint32_t*)(fhiRow + 2 * k) = vh;
            *(uint32_t*)(floRow + 2 * k) = vl;
        }
    }
    __syncthreads();

    // ---- wmma mainloop: 8 warps, each 64(out) x 32(px) ----
    const int wid = tid >> 5;
    const int wm  = wid & 1;        // M half (64 rows)
    const int wn  = wid >> 1;       // N quarter (32 cols)

    wmma::fragment<wmma::accumulator, 16, 16, 16, float> c[4][2];
    #pragma unroll
    for (int i = 0; i < 4; i++)
        #pragma unroll
        for (int j = 0; j < 2; j++) wmma::fill_fragment(c[i][j], 0.f);

    #pragma unroll
    for (int ks = 0; ks < 8; ks++) {
        const int k0 = ks * 16;
        wmma::fragment<wmma::matrix_a, 16, 16, 16, __nv_bfloat16, wmma::row_major> ah[4], al[4];
        wmma::fragment<wmma::matrix_b, 16, 16, 16, __nv_bfloat16, wmma::col_major> bh[2], bl[2];
        #pragma unroll
        for (int i = 0; i < 4; i++) {
            int m0 = wm * 64 + i * 16;
            wmma::load_matrix_sync(ah[i], Whi + m0 * LDW + k0, LDW);
            wmma::load_matrix_sync(al[i], Wlo + m0 * LDW + k0, LDW);
        }
        #pragma unroll
        for (int j = 0; j < 2; j++) {
            int n0 = wn * 32 + j * 16;
            wmma::load_matrix_sync(bh[j], Fhi + n0 * LDW + k0, LDW);
            wmma::load_matrix_sync(bl[j], Flo + n0 * LDW + k0, LDW);
        }
        #pragma unroll
        for (int i = 0; i < 4; i++)
            #pragma unroll
            for (int j = 0; j < 2; j++) {
                wmma::mma_sync(c[i][j], ah[i], bh[j], c[i][j]);
                wmma::mma_sync(c[i][j], ah[i], bl[j], c[i][j]);
                wmma::mma_sync(c[i][j], al[i], bh[j], c[i][j]);
            }
    }
    __syncthreads();

    // ---- stage accumulators to smem, then relu(+hf) coalesced store ----
    float* stage = (float*)sm;   // [128][LDSTG]
    #pragma unroll
    for (int i = 0; i < 4; i++)
        #pragma unroll
        for (int j = 0; j < 2; j++)
            wmma::store_matrix_sync(stage + (wm * 64 + i * 16) * LDSTG + wn * 32 + j * 16,
                                    c[i][j], LDSTG, wmma::mem_row_major);
    __syncthreads();

    const int lid = tid & 31;
    #pragma unroll
    for (int j = 0; j < 16; j++) {
        int o = wid * 16 + j;
        float hf = g_hf[o];
        float4 v = *(float4*)&stage[o * LDSTG + lid * 4];
        v.x = fmaxf(v.x + hf, 0.f);
        v.y = fmaxf(v.y + hf, 0.f);
        v.z = fmaxf(v.z + hf, 0.f);
        v.w = fmaxf(v.w + hf, 0.f);
        *(float4*)(g_Y + o * NPIX + gp0 + lid * 4) = v;
    }
}

// ---------------------------------------------------------------- pass2
// Block = 128 consecutive px in one image row. Per channel: stage 3 Y rows
// (mask+border kill folded in as -1e30) into double-buffered smem; 9-LDS
// window max; fused ew epilogue.
#define KILLV (-1e30f)

__global__ void __launch_bounds__(128)
pass2_kernel(const float* __restrict__ cart, const unsigned int* __restrict__ mk,
             float* __restrict__ out_geo, float* __restrict__ out_cart) {
    __shared__ float4 s_pw[Cc];
    __shared__ float4 s_ew[Cc];
    __shared__ float  sY[2][3][LDSTG];

    const int t = threadIdx.x;
    s_pw[t] = g_pw4[t];
    s_ew[t] = g_ew4[t];

    const int gp = (blockIdx.x << 7) + t;
    const int b  = gp >> 15;
    const int p  = gp & (HW - 1);
    const int y  = p >> 9;
    const int x  = p & (Wd - 1);
    const int x0 = x & ~127;
    const int bbase = b << 15;

    // row bases (clamped) + validity
    int  rowp[3];
    bool rowv[3];
#pragma unroll
    for (int r = 0; r < 3; r++) {
        int yy = y - 1 + r;
        rowv[r] = (yy >= 0) && (yy < Hd);
        rowp[r] = bbase + (rowv[r] ? yy : y) * Wd;
    }

    // per-thread kill (own column), computed once
    float kr[3];
#pragma unroll
    for (int r = 0; r < 3; r++) {
        int off = rowp[r] + x;
        kr[r] = (rowv[r] && (__ldg(mk + off) != 0u)) ? 0.f : KILLV;
    }

    // edge cells: threads 0..5 own (row r, side s)
    const bool eact = (t < 6);
    int er = 0, ecol = 0, eoff = 0;
    float ekill = KILLV;
    if (eact) {
        er = t >> 1;
        int side = t & 1;
        int ex = side ? (x0 + 128) : (x0 - 1);
        bool cv = side ? (x0 + 128 < Wd) : (x0 > 0);
        int exc = cv ? ex : x0;
        eoff = rowp[er] + exc;
        ecol = side ? 129 : 0;
        ekill = (rowv[er] && cv && (__ldg(mk + eoff) != 0u)) ? 0.f : KILLV;
    }

    // relative coordinates of 9 neighbors (garbage where killed — harmless)
    const float* cb = cart + b * 3 * HW;
    const float ccx = __ldg(cb + p);
    const float ccy = __ldg(cb + HW + p);
    const float ccz = __ldg(cb + 2 * HW + p);
    float rx[9], ry[9], rz[9];
#pragma unroll
    for (int kh = 0; kh < 3; kh++) {
#pragma unroll
        for (int kw = 0; kw < 3; kw++) {
            int n = kh * 3 + kw;
            int xx = x + kw - 1;
            int pl = (rowp[kh] & (HW - 1)) + ((xx >= 0 && xx < Wd) ? xx : x);
            rx[n] = __ldg(cb + pl) - ccx;
            ry[n] = __ldg(cb + HW + pl) - ccy;
            rz[n] = __ldg(cb + 2 * HW + pl) - ccz;
        }
    }

    // prefetch channel 0
    float yv[3], yedge = 0.f;
#pragma unroll
    for (int r = 0; r < 3; r++) yv[r] = g_Y[rowp[r] + x] + kr[r];
    if (eact) yedge = g_Y[eoff] + ekill;

    float e0 = 0.f, e1 = 0.f, e2 = 0.f;
    float* og = out_geo + b * Cc * HW + p;

    for (int o = 0; o < Cc; o++) {
        const int cur = o & 1;
        sY[cur][0][t + 1] = yv[0];
        sY[cur][1][t + 1] = yv[1];
        sY[cur][2][t + 1] = yv[2];
        if (eact) sY[cur][er][ecol] = yedge;
        __syncthreads();

        if (o < Cc - 1) {
            const float* Yn = g_Y + (o + 1) * NPIX;
#pragma unroll
            for (int r = 0; r < 3; r++) yv[r] = Yn[rowp[r] + x] + kr[r];
            if (eact) yedge = Yn[eoff] + ekill;
        }

        const float4 pwv = s_pw[o];
        float gm = 0.f;
#pragma unroll
        for (int kh = 0; kh < 3; kh++) {
#pragma unroll
            for (int kw = 0; kw < 3; kw++) {
                int n = kh * 3 + kw;
                float d = fmaf(pwv.x, rx[n], fmaf(pwv.y, ry[n], fmaf(pwv.z, rz[n], pwv.w)));
                float fe = sY[cur][kh][t + kw] + fmaxf(d, 0.f);
                gm = fmaxf(gm, fe);
            }
        }
        og[o * HW] = gm;
        const float4 e = s_ew[o];
        e0 = fmaf(e.x, gm, e0);
        e1 = fmaf(e.y, gm, e1);
        e2 = fmaf(e.z, gm, e2);
    }

    const float mc = (__ldg(mk + gp) != 0u) ? 1.f : 0.f;
    float ev[3] = {e0, e1, e2};
#pragma unroll
    for (int k = 0; k < 3; k++) {
        int ci = (b * 3 + k) * HW + p;
        out_cart[ci] = __ldg(cart + ci) + (ev[k] + g_she[k]) * mc;
    }
}

// ---------------------------------------------------------------- launch
extern "C" void kernel_launch(void* const* d_in, const int* in_sizes, int n_in,
                              void* d_out, int out_size) {
    const float* feat = (const float*)d_in[0];
    const float* cart = (const float*)d_in[1];
    const unsigned int* mask = (const unsigned int*)d_in[2];
    const float* pw = (const float*)d_in[3];
    const float* pg = (const float*)d_in[4];
    const float* pb = (const float*)d_in[5];
    const float* pm = (const float*)d_in[6];
    const float* pv = (const float*)d_in[7];
    const float* fw = (const float*)d_in[8];
    const float* fg = (const float*)d_in[9];
    const float* fb = (const float*)d_in[10];
    const float* fm = (const float*)d_in[11];
    const float* fv = (const float*)d_in[12];
    const float* ew = (const float*)d_in[13];
    const float* eg = (const float*)d_in[14];
    const float* eb = (const float*)d_in[15];
    const float* em = (const float*)d_in[16];
    const float* ev = (const float*)d_in[17];
    (void)in_sizes; (void)n_in; (void)out_size;

    float* out_geo  = (float*)d_out;                        // (B,128,H,W)
    float* out_cart = (float*)d_out + (size_t)Bd * Cc * HW; // (B,3,H,W)

    cudaFuncSetAttribute(pass1_wmma, cudaFuncAttributeMaxDynamicSharedMemorySize, SM_TOT);

    prep_kernel<<<65, 256>>>(fw, fg, fb, fm, fv, pw, pg, pb, pm, pv,
                             ew, eg, eb, em, ev);
    pass1_wmma<<<NPIX / 128, 256, SM_TOT>>>(feat);
    pass2_kernel<<<NPIX / 128, 128>>>(cart, mask, out_geo, out_cart);
}

// round 9
// speedup vs baseline: 1.4429x; 1.4429x over previous
#include <cuda_runtime.h>
#include <cuda_bf16.h>
#include <mma.h>
#include <cstdint>

using namespace nvcuda;

#define Bd   2
#define Cc   128
#define Hd   64
#define Wd   512
#define HW   (Hd*Wd)          // 32768
#define NPIX (Bd*HW)          // 65536
#define EPS  1e-5f

#define LDW   136             // bf16 leading dim in smem (272B rows)
#define NPXT  64              // px tile per pass1 block
#define LDST  68              // f32 stage leading dim

// ---------------- device scratch (allocation-free) ----------------
__device__ __align__(16) float         g_Y[Cc * NPIX];   // [o][gp]
__device__ __align__(16) __nv_bfloat16 g_Whi[Cc * Cc];   // [o][c] fw*scale_f hi
__device__ __align__(16) __nv_bfloat16 g_Wlo[Cc * Cc];   // residual lo
__device__ __align__(16) float         g_E[12 * NPIX];   // [k*4+grp][gp] partial ew sums
__device__ float  g_hf[Cc];
__device__ float4 g_pw4[Cc];                             // {pw*sp (x3), hp}
__device__ float4 g_ew4[Cc];                             // {ew*se (x3), 0}
__device__ float  g_she[3];

// ---------------------------------------------------------------- prep
__global__ void prep_kernel(const float* __restrict__ fw,
                            const float* __restrict__ fg, const float* __restrict__ fb,
                            const float* __restrict__ fm, const float* __restrict__ fv,
                            const float* __restrict__ pw,
                            const float* __restrict__ pg, const float* __restrict__ pb,
                            const float* __restrict__ pm, const float* __restrict__ pv,
                            const float* __restrict__ ew,
                            const float* __restrict__ eg, const float* __restrict__ eb,
                            const float* __restrict__ em, const float* __restrict__ ev) {
    const int tid = threadIdx.x;
    if (blockIdx.x < 64) {
        int i = (blockIdx.x << 8) + tid;      // 0..16383
        int o = i >> 7;
        float sf = fg[o] * rsqrtf(fv[o] + EPS);
        float w = fw[i] * sf;
        __nv_bfloat16 hi = __float2bfloat16(w);
        __nv_bfloat16 lo = __float2bfloat16(w - __bfloat162float(hi));
        g_Whi[i] = hi;
        g_Wlo[i] = lo;
    } else if (tid < Cc) {
        int o = tid;
        float sf = fg[o] * rsqrtf(fv[o] + EPS);
        g_hf[o] = fb[o] - fm[o] * sf;
        float sp = pg[o] * rsqrtf(pv[o] + EPS);
        float hp = pb[o] - pm[o] * sp;
        g_pw4[o] = make_float4(pw[3*o]*sp, pw[3*o+1]*sp, pw[3*o+2]*sp, hp);
        float se0 = eg[0] * rsqrtf(ev[0] + EPS);
        float se1 = eg[1] * rsqrtf(ev[1] + EPS);
        float se2 = eg[2] * rsqrtf(ev[2] + EPS);
        g_ew4[o] = make_float4(ew[o]*se0, ew[Cc+o]*se1, ew[2*Cc+o]*se2, 0.f);
        if (o < 3) {
            float se = eg[o] * rsqrtf(ev[o] + EPS);
            g_she[o] = eb[o] - em[o] * se;
        }
    }
}

// ---------------------------------------------------------------- pass1 (wmma, 2 CTA/SM)
// Per block: D[128 out][64 px], 3-term bf16 split, f32 accum.
// smem: Whi(34816) | Wlo(34816) | Fhi(17408) | Flo(17408) = 104448 B.
// Epilogue stage (f32 [128][LDST] = 34816B) reuses the F region.
#define SEG_W 34816
#define SEG_F 17408
#define SM_TOT (2 * SEG_W + 2 * SEG_F)

__global__ void __launch_bounds__(256, 2)
pass1_wmma(const float* __restrict__ feat) {
    extern __shared__ __align__(16) char sm[];
    __nv_bfloat16* Whi = (__nv_bfloat16*)(sm);
    __nv_bfloat16* Wlo = (__nv_bfloat16*)(sm + SEG_W);
    __nv_bfloat16* Fhi = (__nv_bfloat16*)(sm + 2 * SEG_W);
    __nv_bfloat16* Flo = (__nv_bfloat16*)(sm + 2 * SEG_W + SEG_F);

    const int tid = threadIdx.x;
    const int gp0 = blockIdx.x * NPXT;
    const int b   = gp0 >> 15;
    const int p0  = gp0 & (HW - 1);

    // ---- W hi/lo into padded smem (row r: 16 float4) ----
    {
        const float4* shi = (const float4*)g_Whi;
        const float4* slo = (const float4*)g_Wlo;
        #pragma unroll
        for (int it = 0; it < 8; it++) {
            int idx = tid + (it << 8);           // 0..2047
            int r = idx >> 4, s = idx & 15;
            ((float4*)((char*)Whi + r * (LDW * 2)))[s] = shi[r * 16 + s];
            ((float4*)((char*)Wlo + r * (LDW * 2)))[s] = slo[r * 16 + s];
        }
    }

    // ---- F tile fp32 -> bf16 hi/lo, [px][k] padded smem ----
    {
        const float* fbase = feat + b * Cc * HW + p0;
        const int px = tid & 63;
        const int kg = tid >> 6;                 // 0..3 (32 k each)
        char* fhiRow = (char*)Fhi + px * (LDW * 2);
        char* floRow = (char*)Flo + px * (LDW * 2);
        #pragma unroll 8
        for (int j = 0; j < 16; j++) {
            int k = kg * 32 + 2 * j;
            float f0 = __ldg(fbase + k * HW + px);
            float f1 = __ldg(fbase + (k + 1) * HW + px);
            __nv_bfloat16 h0 = __float2bfloat16(f0);
            __nv_bfloat16 h1 = __float2bfloat16(f1);
            __nv_bfloat16 l0 = __float2bfloat16(f0 - __bfloat162float(h0));
            __nv_bfloat16 l1 = __float2bfloat16(f1 - __bfloat162float(h1));
            uint32_t vh = (uint32_t)__bfloat16_as_ushort(h0) | ((uint32_t)__bfloat16_as_ushort(h1) << 16);
            uint32_t vl = (uint32_t)__bfloat16_as_ushort(l0) | ((uint32_t)__bfloat16_as_ushort(l1) << 16);
            *(uint32_t*)(fhiRow + 2 * k) = vh;
            *(uint32_t*)(floRow + 2 * k) = vl;
        }
    }
    __syncthreads();

    // ---- wmma mainloop: 8 warps, each 32(out) x 32(px) ----
    const int wid = tid >> 5;
    const int wm  = wid & 3;        // M quarter (32 rows)
    const int wn  = wid >> 2;       // N half (32 cols)

    wmma::fragment<wmma::accumulator, 16, 16, 16, float> c[2][2];
    #pragma unroll
    for (int i = 0; i < 2; i++)
        #pragma unroll
        for (int j = 0; j < 2; j++) wmma::fill_fragment(c[i][j], 0.f);

    #pragma unroll
    for (int ks = 0; ks < 8; ks++) {
        const int k0 = ks * 16;
        wmma::fragment<wmma::matrix_a, 16, 16, 16, __nv_bfloat16, wmma::row_major> ah[2], al[2];
        wmma::fragment<wmma::matrix_b, 16, 16, 16, __nv_bfloat16, wmma::col_major> bh[2], bl[2];
        #pragma unroll
        for (int i = 0; i < 2; i++) {
            int m0 = wm * 32 + i * 16;
            wmma::load_matrix_sync(ah[i], Whi + m0 * LDW + k0, LDW);
            wmma::load_matrix_sync(al[i], Wlo + m0 * LDW + k0, LDW);
        }
        #pragma unroll
        for (int j = 0; j < 2; j++) {
            int n0 = wn * 32 + j * 16;
            wmma::load_matrix_sync(bh[j], Fhi + n0 * LDW + k0, LDW);
            wmma::load_matrix_sync(bl[j], Flo + n0 * LDW + k0, LDW);
        }
        #pragma unroll
        for (int i = 0; i < 2; i++)
            #pragma unroll
            for (int j = 0; j < 2; j++) {
                wmma::mma_sync(c[i][j], ah[i], bh[j], c[i][j]);
                wmma::mma_sync(c[i][j], ah[i], bl[j], c[i][j]);
                wmma::mma_sync(c[i][j], al[i], bh[j], c[i][j]);
            }
    }
    __syncthreads();

    // ---- stage accumulators (reuse F region), relu(+hf), coalesced STG ----
    float* stage = (float*)(sm + 2 * SEG_W);   // [128][LDST]
    #pragma unroll
    for (int i = 0; i < 2; i++)
        #pragma unroll
        for (int j = 0; j < 2; j++)
            wmma::store_matrix_sync(stage + (wm * 32 + i * 16) * LDST + wn * 32 + j * 16,
                                    c[i][j], LDST, wmma::mem_row_major);
    __syncthreads();

    const int lid = tid & 31;
    const int f4  = lid & 15;       // float4 index within row (64 px = 16 float4)
    const int ro  = lid >> 4;       // row sub-offset (2 rows per warp-iter)
    #pragma unroll
    for (int j = 0; j < 8; j++) {
        int o = wid * 16 + 2 * j + ro;
        float hf = g_hf[o];
        float4 v = *(float4*)&stage[o * LDST + f4 * 4];
        v.x = fmaxf(v.x + hf, 0.f);
        v.y = fmaxf(v.y + hf, 0.f);
        v.z = fmaxf(v.z + hf, 0.f);
        v.w = fmaxf(v.w + hf, 0.f);
        *(float4*)(g_Y + o * NPIX + gp0 + f4 * 4) = v;
    }
}

// ---------------------------------------------------------------- pass2
// grid (512 strips, 4 channel groups). Thread = pixel; 32 channels per block.
// R2-proven 9-LDG body; writes geo + partial ew sums to g_E.
__global__ void __launch_bounds__(128)
pass2_kernel(const float* __restrict__ cart, const unsigned int* __restrict__ mk,
             float* __restrict__ out_geo) {
    const int gp = (blockIdx.x << 7) + threadIdx.x;
    const int grp = blockIdx.y;
    const int o0  = grp << 5;
    const int b  = gp >> 15;
    const int p  = gp & (HW - 1);
    const int y  = p >> 9;
    const int x  = p & (Wd - 1);

    const float* cb = cart + b * 3 * HW;
    const float ccx = __ldg(cb + p);
    const float ccy = __ldg(cb + HW + p);
    const float ccz = __ldg(cb + 2 * HW + p);

    int   off[9];
    float am[9], rx[9], ry[9], rz[9];
#pragma unroll
    for (int kh = 0; kh < 3; kh++) {
#pragma unroll
        for (int kw = 0; kw < 3; kw++) {
            int n = kh * 3 + kw;
            int yy = y + kh - 1, xx = x + kw - 1;
            bool v = (yy >= 0) && (yy < Hd) && (xx >= 0) && (xx < Wd);
            int pn = yy * Wd + xx;
            int o  = v ? ((b << 15) + pn) : gp;
            off[n] = o;
            am[n]  = (v && (__ldg(mk + o) != 0u)) ? 1.f : 0.f;
            int pl = o & (HW - 1);
            rx[n] = __ldg(cb + pl) - ccx;
            ry[n] = __ldg(cb + HW + pl) - ccy;
            rz[n] = __ldg(cb + 2 * HW + pl) - ccz;
        }
    }

    float e0 = 0.f, e1 = 0.f, e2 = 0.f;
    float* og = out_geo + b * Cc * HW + p;

#pragma unroll 2
    for (int oc = 0; oc < 32; oc++) {
        const int o = o0 + oc;
        const float4 pwv = __ldg(&g_pw4[o]);
        const float* Yo = g_Y + o * NPIX;
        float gm = 0.f;
#pragma unroll
        for (int n = 0; n < 9; n++) {
            float pos = fmaxf(fmaf(pwv.x, rx[n], fmaf(pwv.y, ry[n], fmaf(pwv.z, rz[n], pwv.w))), 0.f);
            float fe  = __ldg(Yo + off[n]) + pos;
            gm = fmaxf(gm, am[n] * fe);
        }
        og[o * HW] = gm;
        const float4 e = __ldg(&g_ew4[o]);
        e0 = fmaf(e.x, gm, e0);
        e1 = fmaf(e.y, gm, e1);
        e2 = fmaf(e.z, gm, e2);
    }

    g_E[(0 * 4 + grp) * NPIX + gp] = e0;
    g_E[(1 * 4 + grp) * NPIX + gp] = e1;
    g_E[(2 * 4 + grp) * NPIX + gp] = e2;
}

// ---------------------------------------------------------------- fixup (cart_out)
__global__ void __launch_bounds__(256)
fixup_kernel(const float* __restrict__ cart, const unsigned int* __restrict__ mk,
             float* __restrict__ out_cart) {
    const int gp = blockIdx.x * 256 + threadIdx.x;
    const int b  = gp >> 15;
    const int p  = gp & (HW - 1);
    const float mc = (__ldg(mk + gp) != 0u) ? 1.f : 0.f;
#pragma unroll
    for (int k = 0; k < 3; k++) {
        const float* Ek = g_E + k * 4 * NPIX;
        float s = Ek[gp] + Ek[NPIX + gp] + Ek[2 * NPIX + gp] + Ek[3 * NPIX + gp];
        int ci = (b * 3 + k) * HW + p;
        out_cart[ci] = __ldg(cart + ci) + (s + g_she[k]) * mc;
    }
}

// ---------------------------------------------------------------- launch
extern "C" void kernel_launch(void* const* d_in, const int* in_sizes, int n_in,
                              void* d_out, int out_size) {
    const float* feat = (const float*)d_in[0];
    const float* cart = (const float*)d_in[1];
    const unsigned int* mask = (const unsigned int*)d_in[2];
    const float* pw = (const float*)d_in[3];
    const float* pg = (const float*)d_in[4];
    const float* pb = (const float*)d_in[5];
    const float* pm = (const float*)d_in[6];
    const float* pv = (const float*)d_in[7];
    const float* fw = (const float*)d_in[8];
    const float* fg = (const float*)d_in[9];
    const float* fb = (const float*)d_in[10];
    const float* fm = (const float*)d_in[11];
    const float* fv = (const float*)d_in[12];
    const float* ew = (const float*)d_in[13];
    const float* eg = (const float*)d_in[14];
    const float* eb = (const float*)d_in[15];
    const float* em = (const float*)d_in[16];
    const float* ev = (const float*)d_in[17];
    (void)in_sizes; (void)n_in; (void)out_size;

    float* out_geo  = (float*)d_out;                        // (B,128,H,W)
    float* out_cart = (float*)d_out + (size_t)Bd * Cc * HW; // (B,3,H,W)

    cudaFuncSetAttribute(pass1_wmma, cudaFuncAttributeMaxDynamicSharedMemorySize, SM_TOT);

    prep_kernel<<<65, 256>>>(fw, fg, fb, fm, fv, pw, pg, pb, pm, pv,
                             ew, eg, eb, em, ev);
    pass1_wmma<<<NPIX / NPXT, 256, SM_TOT>>>(feat);
    dim3 g2(NPIX / 128, 4);
    pass2_kernel<<<g2, 128>>>(cart, mask, out_geo);
    fixup_kernel<<<NPIX / 256, 256>>>(cart, mask, out_cart);
}